// round 13
// baseline (speedup 1.0000x reference)
#include <cuda_runtime.h>

// ---------------------------------------------------------------------------
// Triaffine: out[b,z,x,y] = sum_{i,k,j} xb[b,x,i] * z[b,z,k] * W[i,k,j] * yb[b,y,j]
// B=8, S=128, D=512; W: [513, 512, 513] fp32.
//
// 3-stage GEMM chain (fp32, packed f32x2 FMA):
//   stage1: T[(b,x), k, j'] = Xb[1024,528] @ Wp[528, 512*528]
//   stage2: Q[(b,x), k, y]  = T_p[512,528] @ Yb_b^T[528,128]   (1024 batches)
//   stage3: out[b,z,x,y]    = Z_b[128,512] @ Q_p[512,128]       (1024 batches)
// j and i padded 513 -> 528 (33 k-tiles of 16) so all tiles are guard-free.
// ---------------------------------------------------------------------------

#define J_PAD 528
#define N1    (512 * J_PAD)      // 270336, stage-1 N / T row length
#define KW    262656             // 512*513, weight (k,j) plane per i

// Scratch (device globals: allocation-free per harness rules)
__device__ float g_Xb[1024 * J_PAD];                       //   2.1 MB
__device__ float g_Yb[1024 * J_PAD];                       //   2.1 MB
__device__ float g_Wp[(size_t)J_PAD * N1];                 // 571   MB
__device__ float g_T [(size_t)1024 * 512 * J_PAD];         // 1.11  GB
__device__ float g_Q [(size_t)1024 * 512 * 128];           // 268   MB

// ---------------- packed f32x2 helpers ----------------
__device__ __forceinline__ unsigned long long dup2(float a) {
    unsigned long long r;
    asm("mov.b64 %0, {%1, %1};" : "=l"(r) : "f"(a));
    return r;
}
__device__ __forceinline__ void ffma2(unsigned long long& c,
                                      unsigned long long a,
                                      unsigned long long b) {
    asm("fma.rn.f32x2 %0, %1, %2, %0;" : "+l"(c) : "l"(a), "l"(b));
}
__device__ __forceinline__ float2 unpk(unsigned long long v) {
    float2 r;
    asm("mov.b64 {%0, %1}, %2;" : "=f"(r.x), "=f"(r.y) : "l"(v));
    return r;
}

// ---------------- prep kernels ----------------
__global__ void prep_xy(const float* __restrict__ x, const float* __restrict__ y) {
    int idx = blockIdx.x * 256 + threadIdx.x;
    if (idx >= 1024 * J_PAD) return;
    int m = idx / J_PAD;
    int j = idx - m * J_PAD;
    float vx, vy;
    if (j < 512)      { vx = x[m * 512 + j]; vy = y[m * 512 + j]; }
    else if (j == 512){ vx = 1.0f;           vy = 1.0f; }
    else              { vx = 0.0f;           vy = 0.0f; }
    g_Xb[idx] = vx;
    g_Yb[idx] = vy;
}

// Repack W [513,512,513] -> Wp [528, 512*528] (zero-padded): makes stage-1
// B-operand loads float4-aligned and guard-free.
__global__ void repack_w(const float* __restrict__ W) {
    int idx = blockIdx.x * 256 + threadIdx.x;   // total 528*270336 = 142,737,408
    int i = idx / N1;
    int r = idx - i * N1;
    int k = r / J_PAD;
    int j = r - k * J_PAD;
    float v = 0.0f;
    if (i < 513 && j < 513) v = W[(size_t)i * KW + k * 513 + j];
    g_Wp[idx] = v;
}

// ---------------- 128x128x16 microkernel (shared) ----------------
// As: duplicated-A ({a,a} u64) [16][128]; Bs: fp32 [16][128].
// Thread computes 8x8 tile at (m0, n0) via 32 f32x2 FMAs per k-step.
__device__ __forceinline__ void mma_tile(const unsigned long long (*As)[128],
                                         const float (*Bsr)[128],
                                         int m0, int n0,
                                         unsigned long long acc[8][4]) {
#pragma unroll
    for (int kk = 0; kk < 16; ++kk) {
        const ulonglong2* pA = reinterpret_cast<const ulonglong2*>(&As[kk][m0]);
        ulonglong2 a0 = pA[0], a1 = pA[1], a2 = pA[2], a3 = pA[3];
        const ulonglong2* pB = reinterpret_cast<const ulonglong2*>(&Bsr[kk][n0]);
        ulonglong2 b0 = pB[0], b1 = pB[1];
        unsigned long long a[8] = {a0.x, a0.y, a1.x, a1.y, a2.x, a2.y, a3.x, a3.y};
        unsigned long long b[4] = {b0.x, b0.y, b1.x, b1.y};
#pragma unroll
        for (int i = 0; i < 8; ++i)
#pragma unroll
            for (int q = 0; q < 4; ++q)
                ffma2(acc[i][q], a[i], b[q]);
    }
}

// ---------------- stage 1: T = Xb @ Wp ----------------
// M=1024, N=270336, K=528. Grid (2112, 8), 256 threads.
__global__ __launch_bounds__(256) void sgemm1() {
    __shared__ __align__(16) unsigned long long As2[2][16][128];  // 32 KB
    __shared__ __align__(16) float              Bs [2][16][128];  // 16 KB
    const int tid  = threadIdx.x;
    const int nblk = blockIdx.x * 128;
    const int mblk = blockIdx.y * 128;
    const int m0 = (tid & 15) * 8;
    const int n0 = (tid >> 4) * 8;
    const int am = tid >> 2,  ac = (tid & 3) * 4;   // A: rows am, am+64
    const int br = tid >> 5,  bc = (tid & 31) * 4;  // B: rows br, br+8

    // prologue: tile 0 -> buffer 0
#pragma unroll
    for (int s = 0; s < 2; ++s) {
        float4 ra = *reinterpret_cast<const float4*>(
            &g_Xb[(mblk + am + s * 64) * J_PAD + ac]);
        As2[0][ac + 0][am + s * 64] = dup2(ra.x);
        As2[0][ac + 1][am + s * 64] = dup2(ra.y);
        As2[0][ac + 2][am + s * 64] = dup2(ra.z);
        As2[0][ac + 3][am + s * 64] = dup2(ra.w);
        float4 rb = *reinterpret_cast<const float4*>(
            &g_Wp[(size_t)(br + s * 8) * N1 + nblk + bc]);
        *reinterpret_cast<float4*>(&Bs[0][br + s * 8][bc]) = rb;
    }
    __syncthreads();

    unsigned long long acc[8][4];
#pragma unroll
    for (int i = 0; i < 8; ++i)
#pragma unroll
        for (int q = 0; q < 4; ++q) acc[i][q] = 0ull;

    const int KT = J_PAD / 16;  // 33
    for (int kt = 0; kt < KT; ++kt) {
        const int cur = kt & 1;
        float4 pa0, pa1, pb0, pb1;
        const bool pre = (kt + 1 < KT);
        if (pre) {
            pa0 = *reinterpret_cast<const float4*>(
                &g_Xb[(mblk + am) * J_PAD + (kt + 1) * 16 + ac]);
            pa1 = *reinterpret_cast<const float4*>(
                &g_Xb[(mblk + am + 64) * J_PAD + (kt + 1) * 16 + ac]);
            pb0 = *reinterpret_cast<const float4*>(
                &g_Wp[(size_t)((kt + 1) * 16 + br) * N1 + nblk + bc]);
            pb1 = *reinterpret_cast<const float4*>(
                &g_Wp[(size_t)((kt + 1) * 16 + br + 8) * N1 + nblk + bc]);
        }
        mma_tile(As2[cur], Bs[cur], m0, n0, acc);
        if (pre) {
            const int nx = cur ^ 1;
            As2[nx][ac + 0][am]      = dup2(pa0.x);
            As2[nx][ac + 1][am]      = dup2(pa0.y);
            As2[nx][ac + 2][am]      = dup2(pa0.z);
            As2[nx][ac + 3][am]      = dup2(pa0.w);
            As2[nx][ac + 0][am + 64] = dup2(pa1.x);
            As2[nx][ac + 1][am + 64] = dup2(pa1.y);
            As2[nx][ac + 2][am + 64] = dup2(pa1.z);
            As2[nx][ac + 3][am + 64] = dup2(pa1.w);
            *reinterpret_cast<float4*>(&Bs[nx][br][bc])     = pb0;
            *reinterpret_cast<float4*>(&Bs[nx][br + 8][bc]) = pb1;
        }
        __syncthreads();
    }

#pragma unroll
    for (int i = 0; i < 8; ++i) {
        float2 t0 = unpk(acc[i][0]), t1 = unpk(acc[i][1]);
        float2 t2 = unpk(acc[i][2]), t3 = unpk(acc[i][3]);
        float* dst = &g_T[(size_t)(mblk + m0 + i) * N1 + nblk + n0];
        *reinterpret_cast<float4*>(dst)     = make_float4(t0.x, t0.y, t1.x, t1.y);
        *reinterpret_cast<float4*>(dst + 4) = make_float4(t2.x, t2.y, t3.x, t3.y);
    }
}

// ---------------- stage 2: Q_p = T_p @ Yb_b^T ----------------
// Per batch p=(b,x): M=512(k), N=128(y), K=528(j). Grid (4, 1024).
__global__ __launch_bounds__(256) void sgemm2() {
    __shared__ __align__(16) unsigned long long As2[2][16][128];
    __shared__ __align__(16) float              Bs [2][16][128];
    const int tid  = threadIdx.x;
    const int mblk = blockIdx.x * 128;
    const int p    = blockIdx.y;
    const int b    = p >> 7;
    const float* Ap = &g_T [(size_t)p * 512 * J_PAD];
    const float* Bp = &g_Yb[(size_t)b * 128 * J_PAD];
    const int m0 = (tid & 15) * 8;
    const int n0 = (tid >> 4) * 8;
    const int am = tid >> 2, ac = (tid & 3) * 4;   // A rows am, am+64
    const int yv = tid >> 2, yc = (tid & 3) * 4;   // B (transposed): y rows yv, yv+64

#pragma unroll
    for (int s = 0; s < 2; ++s) {
        float4 ra = *reinterpret_cast<const float4*>(
            &Ap[(mblk + am + s * 64) * J_PAD + ac]);
        As2[0][ac + 0][am + s * 64] = dup2(ra.x);
        As2[0][ac + 1][am + s * 64] = dup2(ra.y);
        As2[0][ac + 2][am + s * 64] = dup2(ra.z);
        As2[0][ac + 3][am + s * 64] = dup2(ra.w);
        float4 rb = *reinterpret_cast<const float4*>(
            &Bp[(yv + s * 64) * J_PAD + yc]);
        Bs[0][yc + 0][yv + s * 64] = rb.x;
        Bs[0][yc + 1][yv + s * 64] = rb.y;
        Bs[0][yc + 2][yv + s * 64] = rb.z;
        Bs[0][yc + 3][yv + s * 64] = rb.w;
    }
    __syncthreads();

    unsigned long long acc[8][4];
#pragma unroll
    for (int i = 0; i < 8; ++i)
#pragma unroll
        for (int q = 0; q < 4; ++q) acc[i][q] = 0ull;

    const int KT = J_PAD / 16;  // 33
    for (int kt = 0; kt < KT; ++kt) {
        const int cur = kt & 1;
        float4 pa0, pa1, pb0, pb1;
        const bool pre = (kt + 1 < KT);
        if (pre) {
            pa0 = *reinterpret_cast<const float4*>(
                &Ap[(mblk + am) * J_PAD + (kt + 1) * 16 + ac]);
            pa1 = *reinterpret_cast<const float4*>(
                &Ap[(mblk + am + 64) * J_PAD + (kt + 1) * 16 + ac]);
            pb0 = *reinterpret_cast<const float4*>(
                &Bp[yv * J_PAD + (kt + 1) * 16 + yc]);
            pb1 = *reinterpret_cast<const float4*>(
                &Bp[(yv + 64) * J_PAD + (kt + 1) * 16 + yc]);
        }
        mma_tile(As2[cur], Bs[cur], m0, n0, acc);
        if (pre) {
            const int nx = cur ^ 1;
            As2[nx][ac + 0][am]      = dup2(pa0.x);
            As2[nx][ac + 1][am]      = dup2(pa0.y);
            As2[nx][ac + 2][am]      = dup2(pa0.z);
            As2[nx][ac + 3][am]      = dup2(pa0.w);
            As2[nx][ac + 0][am + 64] = dup2(pa1.x);
            As2[nx][ac + 1][am + 64] = dup2(pa1.y);
            As2[nx][ac + 2][am + 64] = dup2(pa1.z);
            As2[nx][ac + 3][am + 64] = dup2(pa1.w);
            Bs[nx][yc + 0][yv]      = pb0.x;
            Bs[nx][yc + 1][yv]      = pb0.y;
            Bs[nx][yc + 2][yv]      = pb0.z;
            Bs[nx][yc + 3][yv]      = pb0.w;
            Bs[nx][yc + 0][yv + 64] = pb1.x;
            Bs[nx][yc + 1][yv + 64] = pb1.y;
            Bs[nx][yc + 2][yv + 64] = pb1.z;
            Bs[nx][yc + 3][yv + 64] = pb1.w;
        }
        __syncthreads();
    }

#pragma unroll
    for (int i = 0; i < 8; ++i) {
        float2 t0 = unpk(acc[i][0]), t1 = unpk(acc[i][1]);
        float2 t2 = unpk(acc[i][2]), t3 = unpk(acc[i][3]);
        float* dst = &g_Q[(size_t)p * 512 * 128 +
                          (size_t)(mblk + m0 + i) * 128 + n0];
        *reinterpret_cast<float4*>(dst)     = make_float4(t0.x, t0.y, t1.x, t1.y);
        *reinterpret_cast<float4*>(dst + 4) = make_float4(t2.x, t2.y, t3.x, t3.y);
    }
}

// ---------------- stage 3: out_bx = Z_b @ Q_p ----------------
// Per batch p=(b,x): M=128(z), N=128(y), K=512. Grid (1024).
__global__ __launch_bounds__(256) void sgemm3(const float* __restrict__ Z,
                                              float* __restrict__ Out) {
    __shared__ __align__(16) unsigned long long As2[2][16][128];
    __shared__ __align__(16) float              Bs [2][16][128];
    const int tid = threadIdx.x;
    const int p   = blockIdx.x;
    const int b   = p >> 7;
    const int x   = p & 127;
    const float* Ap = Z   + (size_t)b * 128 * 512;
    const float* Bp = &g_Q[(size_t)p * 512 * 128];
    float* Cp = Out + (size_t)b * 2097152 + (size_t)x * 128;
    const int m0 = (tid & 15) * 8;
    const int n0 = (tid >> 4) * 8;
    const int am = tid >> 2,  ac = (tid & 3) * 4;
    const int br = tid >> 5,  bc = (tid & 31) * 4;

#pragma unroll
    for (int s = 0; s < 2; ++s) {
        float4 ra = *reinterpret_cast<const float4*>(
            &Ap[(am + s * 64) * 512 + ac]);
        As2[0][ac + 0][am + s * 64] = dup2(ra.x);
        As2[0][ac + 1][am + s * 64] = dup2(ra.y);
        As2[0][ac + 2][am + s * 64] = dup2(ra.z);
        As2[0][ac + 3][am + s * 64] = dup2(ra.w);
        float4 rb = *reinterpret_cast<const float4*>(
            &Bp[(br + s * 8) * 128 + bc]);
        *reinterpret_cast<float4*>(&Bs[0][br + s * 8][bc]) = rb;
    }
    __syncthreads();

    unsigned long long acc[8][4];
#pragma unroll
    for (int i = 0; i < 8; ++i)
#pragma unroll
        for (int q = 0; q < 4; ++q) acc[i][q] = 0ull;

    const int KT = 512 / 16;  // 32
    for (int kt = 0; kt < KT; ++kt) {
        const int cur = kt & 1;
        float4 pa0, pa1, pb0, pb1;
        const bool pre = (kt + 1 < KT);
        if (pre) {
            pa0 = *reinterpret_cast<const float4*>(
                &Ap[am * 512 + (kt + 1) * 16 + ac]);
            pa1 = *reinterpret_cast<const float4*>(
                &Ap[(am + 64) * 512 + (kt + 1) * 16 + ac]);
            pb0 = *reinterpret_cast<const float4*>(
                &Bp[((kt + 1) * 16 + br) * 128 + bc]);
            pb1 = *reinterpret_cast<const float4*>(
                &Bp[((kt + 1) * 16 + br + 8) * 128 + bc]);
        }
        mma_tile(As2[cur], Bs[cur], m0, n0, acc);
        if (pre) {
            const int nx = cur ^ 1;
            As2[nx][ac + 0][am]      = dup2(pa0.x);
            As2[nx][ac + 1][am]      = dup2(pa0.y);
            As2[nx][ac + 2][am]      = dup2(pa0.z);
            As2[nx][ac + 3][am]      = dup2(pa0.w);
            As2[nx][ac + 0][am + 64] = dup2(pa1.x);
            As2[nx][ac + 1][am + 64] = dup2(pa1.y);
            As2[nx][ac + 2][am + 64] = dup2(pa1.z);
            As2[nx][ac + 3][am + 64] = dup2(pa1.w);
            *reinterpret_cast<float4*>(&Bs[nx][br][bc])     = pb0;
            *reinterpret_cast<float4*>(&Bs[nx][br + 8][bc]) = pb1;
        }
        __syncthreads();
    }

#pragma unroll
    for (int i = 0; i < 8; ++i) {
        float2 t0 = unpk(acc[i][0]), t1 = unpk(acc[i][1]);
        float2 t2 = unpk(acc[i][2]), t3 = unpk(acc[i][3]);
        float* dst = Cp + (size_t)(m0 + i) * 16384 + n0;
        *reinterpret_cast<float4*>(dst)     = make_float4(t0.x, t0.y, t1.x, t1.y);
        *reinterpret_cast<float4*>(dst + 4) = make_float4(t2.x, t2.y, t3.x, t3.y);
    }
}

// ---------------- launcher ----------------
extern "C" void kernel_launch(void* const* d_in, const int* in_sizes, int n_in,
                              void* d_out, int out_size) {
    // weight = the largest input; x, y, z = remaining three, in metadata order
    int wi = 0;
    for (int i = 1; i < n_in; ++i)
        if (in_sizes[i] > in_sizes[wi]) wi = i;
    const float* xyz[3] = {nullptr, nullptr, nullptr};
    int c = 0;
    for (int i = 0; i < n_in; ++i)
        if (i != wi && c < 3) xyz[c++] = (const float*)d_in[i];
    const float* x = xyz[0];
    const float* y = xyz[1];
    const float* z = xyz[2];
    const float* w = (const float*)d_in[wi];
    float* out = (float*)d_out;

    prep_xy<<<(1024 * J_PAD) / 256, 256>>>(x, y);
    repack_w<<<(int)(((size_t)J_PAD * N1) / 256), 256>>>(w);

    dim3 g1(N1 / 128, 1024 / 128);   // (2112, 8)
    sgemm1<<<g1, 256>>>();

    dim3 g2(512 / 128, 1024);        // (4, 1024)
    sgemm2<<<g2, 256>>>();

    sgemm3<<<1024, 256>>>(z, out);
}

// round 14
// speedup vs baseline: 1.0012x; 1.0012x over previous
#include <cuda_runtime.h>

// ---------------------------------------------------------------------------
// Triaffine: out[b,z,x,y] = sum_{i,k,j} xb[b,x,i] * z[b,z,k] * W[i,k,j] * yb[b,y,j]
// B=8, S=128, D=512; W: [513, 512, 513] fp32.
//
// 3-stage GEMM chain (fp32, packed f32x2 FMA):
//   stage1: T[(b,x), k, j'] = Xb[1024,528] @ Wp[528, 512*528]
//   stage2: Q[(b,x), k, y]  = T_p[512,528] @ Yb_b^T[528,128]   (1024 batches)
//   stage3: out[b,z,x,y]    = Z_b[128,512] @ Q_p[512,128]       (1024 batches)
// j and i padded 513 -> 528 (33 k-tiles of 16) so all tiles are guard-free.
// ---------------------------------------------------------------------------

#define J_PAD 528
#define N1    (512 * J_PAD)      // 270336, stage-1 N / T row length
#define KW    262656             // 512*513, weight (k,j) plane per i

// Scratch (device globals: allocation-free per harness rules)
__device__ float g_Xb[1024 * J_PAD];                       //   2.1 MB
__device__ float g_Yb[1024 * J_PAD];                       //   2.1 MB
__device__ float g_Wp[(size_t)J_PAD * N1];                 // 571   MB
__device__ float g_T [(size_t)1024 * 512 * J_PAD];         // 1.11  GB
__device__ float g_Q [(size_t)1024 * 512 * 128];           // 268   MB

// ---------------- packed f32x2 helpers ----------------
__device__ __forceinline__ unsigned long long dup2(float a) {
    unsigned long long r;
    asm("mov.b64 %0, {%1, %1};" : "=l"(r) : "f"(a));
    return r;
}
__device__ __forceinline__ void ffma2(unsigned long long& c,
                                      unsigned long long a,
                                      unsigned long long b) {
    asm("fma.rn.f32x2 %0, %1, %2, %0;" : "+l"(c) : "l"(a), "l"(b));
}
__device__ __forceinline__ float2 unpk(unsigned long long v) {
    float2 r;
    asm("mov.b64 {%0, %1}, %2;" : "=f"(r.x), "=f"(r.y) : "l"(v));
    return r;
}

// ---------------- prep kernels ----------------
__global__ void prep_xy(const float* __restrict__ x, const float* __restrict__ y) {
    int idx = blockIdx.x * 256 + threadIdx.x;
    if (idx >= 1024 * J_PAD) return;
    int m = idx / J_PAD;
    int j = idx - m * J_PAD;
    float vx, vy;
    if (j < 512)      { vx = x[m * 512 + j]; vy = y[m * 512 + j]; }
    else if (j == 512){ vx = 1.0f;           vy = 1.0f; }
    else              { vx = 0.0f;           vy = 0.0f; }
    g_Xb[idx] = vx;
    g_Yb[idx] = vy;
}

// Repack W [513,512,513] -> Wp [528, 512*528] (zero-padded): makes stage-1
// B-operand loads float4-aligned and guard-free.
__global__ void repack_w(const float* __restrict__ W) {
    int idx = blockIdx.x * 256 + threadIdx.x;   // total 528*270336 = 142,737,408
    int i = idx / N1;
    int r = idx - i * N1;
    int k = r / J_PAD;
    int j = r - k * J_PAD;
    float v = 0.0f;
    if (i < 513 && j < 513) v = W[(size_t)i * KW + k * 513 + j];
    g_Wp[idx] = v;
}

// ---------------- 128x128x16 microkernel (shared) ----------------
// As: duplicated-A ({a,a} u64) [16][128]; Bs: fp32 [16][128].
// Thread computes 8x8 tile at (m0, n0) via 32 f32x2 FMAs per k-step.
__device__ __forceinline__ void mma_tile(const unsigned long long (*As)[128],
                                         const float (*Bsr)[128],
                                         int m0, int n0,
                                         unsigned long long acc[8][4]) {
#pragma unroll
    for (int kk = 0; kk < 16; ++kk) {
        const ulonglong2* pA = reinterpret_cast<const ulonglong2*>(&As[kk][m0]);
        ulonglong2 a0 = pA[0], a1 = pA[1], a2 = pA[2], a3 = pA[3];
        const ulonglong2* pB = reinterpret_cast<const ulonglong2*>(&Bsr[kk][n0]);
        ulonglong2 b0 = pB[0], b1 = pB[1];
        unsigned long long a[8] = {a0.x, a0.y, a1.x, a1.y, a2.x, a2.y, a3.x, a3.y};
        unsigned long long b[4] = {b0.x, b0.y, b1.x, b1.y};
#pragma unroll
        for (int i = 0; i < 8; ++i)
#pragma unroll
            for (int q = 0; q < 4; ++q)
                ffma2(acc[i][q], a[i], b[q]);
    }
}

// ---------------- stage 1: T = Xb @ Wp ----------------
// M=1024, N=270336, K=528. Grid (2112, 8), 256 threads.
__global__ __launch_bounds__(256) void sgemm1() {
    __shared__ __align__(16) unsigned long long As2[2][16][128];  // 32 KB
    __shared__ __align__(16) float              Bs [2][16][128];  // 16 KB
    const int tid  = threadIdx.x;
    const int nblk = blockIdx.x * 128;
    const int mblk = blockIdx.y * 128;
    const int m0 = (tid & 15) * 8;
    const int n0 = (tid >> 4) * 8;
    const int am = tid >> 2,  ac = (tid & 3) * 4;   // A: rows am, am+64
    const int br = tid >> 5,  bc = (tid & 31) * 4;  // B: rows br, br+8

    // prologue: tile 0 -> buffer 0
#pragma unroll
    for (int s = 0; s < 2; ++s) {
        float4 ra = *reinterpret_cast<const float4*>(
            &g_Xb[(mblk + am + s * 64) * J_PAD + ac]);
        As2[0][ac + 0][am + s * 64] = dup2(ra.x);
        As2[0][ac + 1][am + s * 64] = dup2(ra.y);
        As2[0][ac + 2][am + s * 64] = dup2(ra.z);
        As2[0][ac + 3][am + s * 64] = dup2(ra.w);
        float4 rb = *reinterpret_cast<const float4*>(
            &g_Wp[(size_t)(br + s * 8) * N1 + nblk + bc]);
        *reinterpret_cast<float4*>(&Bs[0][br + s * 8][bc]) = rb;
    }
    __syncthreads();

    unsigned long long acc[8][4];
#pragma unroll
    for (int i = 0; i < 8; ++i)
#pragma unroll
        for (int q = 0; q < 4; ++q) acc[i][q] = 0ull;

    const int KT = J_PAD / 16;  // 33
    for (int kt = 0; kt < KT; ++kt) {
        const int cur = kt & 1;
        float4 pa0, pa1, pb0, pb1;
        const bool pre = (kt + 1 < KT);
        if (pre) {
            pa0 = *reinterpret_cast<const float4*>(
                &g_Xb[(mblk + am) * J_PAD + (kt + 1) * 16 + ac]);
            pa1 = *reinterpret_cast<const float4*>(
                &g_Xb[(mblk + am + 64) * J_PAD + (kt + 1) * 16 + ac]);
            pb0 = *reinterpret_cast<const float4*>(
                &g_Wp[(size_t)((kt + 1) * 16 + br) * N1 + nblk + bc]);
            pb1 = *reinterpret_cast<const float4*>(
                &g_Wp[(size_t)((kt + 1) * 16 + br + 8) * N1 + nblk + bc]);
        }
        mma_tile(As2[cur], Bs[cur], m0, n0, acc);
        if (pre) {
            const int nx = cur ^ 1;
            As2[nx][ac + 0][am]      = dup2(pa0.x);
            As2[nx][ac + 1][am]      = dup2(pa0.y);
            As2[nx][ac + 2][am]      = dup2(pa0.z);
            As2[nx][ac + 3][am]      = dup2(pa0.w);
            As2[nx][ac + 0][am + 64] = dup2(pa1.x);
            As2[nx][ac + 1][am + 64] = dup2(pa1.y);
            As2[nx][ac + 2][am + 64] = dup2(pa1.z);
            As2[nx][ac + 3][am + 64] = dup2(pa1.w);
            *reinterpret_cast<float4*>(&Bs[nx][br][bc])     = pb0;
            *reinterpret_cast<float4*>(&Bs[nx][br + 8][bc]) = pb1;
        }
        __syncthreads();
    }

#pragma unroll
    for (int i = 0; i < 8; ++i) {
        float2 t0 = unpk(acc[i][0]), t1 = unpk(acc[i][1]);
        float2 t2 = unpk(acc[i][2]), t3 = unpk(acc[i][3]);
        float* dst = &g_T[(size_t)(mblk + m0 + i) * N1 + nblk + n0];
        *reinterpret_cast<float4*>(dst)     = make_float4(t0.x, t0.y, t1.x, t1.y);
        *reinterpret_cast<float4*>(dst + 4) = make_float4(t2.x, t2.y, t3.x, t3.y);
    }
}

// ---------------- stage 2: Q_p = T_p @ Yb_b^T ----------------
// Per batch p=(b,x): M=512(k), N=128(y), K=528(j). Grid (4, 1024).
__global__ __launch_bounds__(256) void sgemm2() {
    __shared__ __align__(16) unsigned long long As2[2][16][128];
    __shared__ __align__(16) float              Bs [2][16][128];
    const int tid  = threadIdx.x;
    const int mblk = blockIdx.x * 128;
    const int p    = blockIdx.y;
    const int b    = p >> 7;
    const float* Ap = &g_T [(size_t)p * 512 * J_PAD];
    const float* Bp = &g_Yb[(size_t)b * 128 * J_PAD];
    const int m0 = (tid & 15) * 8;
    const int n0 = (tid >> 4) * 8;
    const int am = tid >> 2, ac = (tid & 3) * 4;   // A rows am, am+64
    const int yv = tid >> 2, yc = (tid & 3) * 4;   // B (transposed): y rows yv, yv+64

#pragma unroll
    for (int s = 0; s < 2; ++s) {
        float4 ra = *reinterpret_cast<const float4*>(
            &Ap[(mblk + am + s * 64) * J_PAD + ac]);
        As2[0][ac + 0][am + s * 64] = dup2(ra.x);
        As2[0][ac + 1][am + s * 64] = dup2(ra.y);
        As2[0][ac + 2][am + s * 64] = dup2(ra.z);
        As2[0][ac + 3][am + s * 64] = dup2(ra.w);
        float4 rb = *reinterpret_cast<const float4*>(
            &Bp[(yv + s * 64) * J_PAD + yc]);
        Bs[0][yc + 0][yv + s * 64] = rb.x;
        Bs[0][yc + 1][yv + s * 64] = rb.y;
        Bs[0][yc + 2][yv + s * 64] = rb.z;
        Bs[0][yc + 3][yv + s * 64] = rb.w;
    }
    __syncthreads();

    unsigned long long acc[8][4];
#pragma unroll
    for (int i = 0; i < 8; ++i)
#pragma unroll
        for (int q = 0; q < 4; ++q) acc[i][q] = 0ull;

    const int KT = J_PAD / 16;  // 33
    for (int kt = 0; kt < KT; ++kt) {
        const int cur = kt & 1;
        float4 pa0, pa1, pb0, pb1;
        const bool pre = (kt + 1 < KT);
        if (pre) {
            pa0 = *reinterpret_cast<const float4*>(
                &Ap[(mblk + am) * J_PAD + (kt + 1) * 16 + ac]);
            pa1 = *reinterpret_cast<const float4*>(
                &Ap[(mblk + am + 64) * J_PAD + (kt + 1) * 16 + ac]);
            pb0 = *reinterpret_cast<const float4*>(
                &Bp[yv * J_PAD + (kt + 1) * 16 + yc]);
            pb1 = *reinterpret_cast<const float4*>(
                &Bp[(yv + 64) * J_PAD + (kt + 1) * 16 + yc]);
        }
        mma_tile(As2[cur], Bs[cur], m0, n0, acc);
        if (pre) {
            const int nx = cur ^ 1;
            As2[nx][ac + 0][am]      = dup2(pa0.x);
            As2[nx][ac + 1][am]      = dup2(pa0.y);
            As2[nx][ac + 2][am]      = dup2(pa0.z);
            As2[nx][ac + 3][am]      = dup2(pa0.w);
            As2[nx][ac + 0][am + 64] = dup2(pa1.x);
            As2[nx][ac + 1][am + 64] = dup2(pa1.y);
            As2[nx][ac + 2][am + 64] = dup2(pa1.z);
            As2[nx][ac + 3][am + 64] = dup2(pa1.w);
            Bs[nx][yc + 0][yv]      = pb0.x;
            Bs[nx][yc + 1][yv]      = pb0.y;
            Bs[nx][yc + 2][yv]      = pb0.z;
            Bs[nx][yc + 3][yv]      = pb0.w;
            Bs[nx][yc + 0][yv + 64] = pb1.x;
            Bs[nx][yc + 1][yv + 64] = pb1.y;
            Bs[nx][yc + 2][yv + 64] = pb1.z;
            Bs[nx][yc + 3][yv + 64] = pb1.w;
        }
        __syncthreads();
    }

#pragma unroll
    for (int i = 0; i < 8; ++i) {
        float2 t0 = unpk(acc[i][0]), t1 = unpk(acc[i][1]);
        float2 t2 = unpk(acc[i][2]), t3 = unpk(acc[i][3]);
        float* dst = &g_Q[(size_t)p * 512 * 128 +
                          (size_t)(mblk + m0 + i) * 128 + n0];
        *reinterpret_cast<float4*>(dst)     = make_float4(t0.x, t0.y, t1.x, t1.y);
        *reinterpret_cast<float4*>(dst + 4) = make_float4(t2.x, t2.y, t3.x, t3.y);
    }
}

// ---------------- stage 3: out_bx = Z_b @ Q_p ----------------
// Per batch p=(b,x): M=128(z), N=128(y), K=512. Grid (1024).
__global__ __launch_bounds__(256) void sgemm3(const float* __restrict__ Z,
                                              float* __restrict__ Out) {
    __shared__ __align__(16) unsigned long long As2[2][16][128];
    __shared__ __align__(16) float              Bs [2][16][128];
    const int tid = threadIdx.x;
    const int p   = blockIdx.x;
    const int b   = p >> 7;
    const int x   = p & 127;
    const float* Ap = Z   + (size_t)b * 128 * 512;
    const float* Bp = &g_Q[(size_t)p * 512 * 128];
    float* Cp = Out + (size_t)b * 2097152 + (size_t)x * 128;
    const int m0 = (tid & 15) * 8;
    const int n0 = (tid >> 4) * 8;
    const int am = tid >> 2,  ac = (tid & 3) * 4;
    const int br = tid >> 5,  bc = (tid & 31) * 4;

#pragma unroll
    for (int s = 0; s < 2; ++s) {
        float4 ra = *reinterpret_cast<const float4*>(
            &Ap[(am + s * 64) * 512 + ac]);
        As2[0][ac + 0][am + s * 64] = dup2(ra.x);
        As2[0][ac + 1][am + s * 64] = dup2(ra.y);
        As2[0][ac + 2][am + s * 64] = dup2(ra.z);
        As2[0][ac + 3][am + s * 64] = dup2(ra.w);
        float4 rb = *reinterpret_cast<const float4*>(
            &Bp[(br + s * 8) * 128 + bc]);
        *reinterpret_cast<float4*>(&Bs[0][br + s * 8][bc]) = rb;
    }
    __syncthreads();

    unsigned long long acc[8][4];
#pragma unroll
    for (int i = 0; i < 8; ++i)
#pragma unroll
        for (int q = 0; q < 4; ++q) acc[i][q] = 0ull;

    const int KT = 512 / 16;  // 32
    for (int kt = 0; kt < KT; ++kt) {
        const int cur = kt & 1;
        float4 pa0, pa1, pb0, pb1;
        const bool pre = (kt + 1 < KT);
        if (pre) {
            pa0 = *reinterpret_cast<const float4*>(
                &Ap[am * 512 + (kt + 1) * 16 + ac]);
            pa1 = *reinterpret_cast<const float4*>(
                &Ap[(am + 64) * 512 + (kt + 1) * 16 + ac]);
            pb0 = *reinterpret_cast<const float4*>(
                &Bp[((kt + 1) * 16 + br) * 128 + bc]);
            pb1 = *reinterpret_cast<const float4*>(
                &Bp[((kt + 1) * 16 + br + 8) * 128 + bc]);
        }
        mma_tile(As2[cur], Bs[cur], m0, n0, acc);
        if (pre) {
            const int nx = cur ^ 1;
            As2[nx][ac + 0][am]      = dup2(pa0.x);
            As2[nx][ac + 1][am]      = dup2(pa0.y);
            As2[nx][ac + 2][am]      = dup2(pa0.z);
            As2[nx][ac + 3][am]      = dup2(pa0.w);
            As2[nx][ac + 0][am + 64] = dup2(pa1.x);
            As2[nx][ac + 1][am + 64] = dup2(pa1.y);
            As2[nx][ac + 2][am + 64] = dup2(pa1.z);
            As2[nx][ac + 3][am + 64] = dup2(pa1.w);
            *reinterpret_cast<float4*>(&Bs[nx][br][bc])     = pb0;
            *reinterpret_cast<float4*>(&Bs[nx][br + 8][bc]) = pb1;
        }
        __syncthreads();
    }

#pragma unroll
    for (int i = 0; i < 8; ++i) {
        float2 t0 = unpk(acc[i][0]), t1 = unpk(acc[i][1]);
        float2 t2 = unpk(acc[i][2]), t3 = unpk(acc[i][3]);
        float* dst = Cp + (size_t)(m0 + i) * 16384 + n0;
        *reinterpret_cast<float4*>(dst)     = make_float4(t0.x, t0.y, t1.x, t1.y);
        *reinterpret_cast<float4*>(dst + 4) = make_float4(t2.x, t2.y, t3.x, t3.y);
    }
}

// ---------------- launcher ----------------
extern "C" void kernel_launch(void* const* d_in, const int* in_sizes, int n_in,
                              void* d_out, int out_size) {
    // weight = the largest input; x, y, z = remaining three, in metadata order
    int wi = 0;
    for (int i = 1; i < n_in; ++i)
        if (in_sizes[i] > in_sizes[wi]) wi = i;
    const float* xyz[3] = {nullptr, nullptr, nullptr};
    int c = 0;
    for (int i = 0; i < n_in; ++i)
        if (i != wi && c < 3) xyz[c++] = (const float*)d_in[i];
    const float* x = xyz[0];
    const float* y = xyz[1];
    const float* z = xyz[2];
    const float* w = (const float*)d_in[wi];
    float* out = (float*)d_out;

    prep_xy<<<(1024 * J_PAD) / 256, 256>>>(x, y);
    repack_w<<<(int)(((size_t)J_PAD * N1) / 256), 256>>>(w);

    dim3 g1(N1 / 128, 1024 / 128);   // (2112, 8)
    sgemm1<<<g1, 256>>>();

    dim3 g2(512 / 128, 1024);        // (4, 1024)
    sgemm2<<<g2, 256>>>();

    sgemm3<<<1024, 256>>>(z, out);
}

// round 15
// speedup vs baseline: 1.0013x; 1.0001x over previous
#include <cuda_runtime.h>

// ---------------------------------------------------------------------------
// Triaffine: out[b,z,x,y] = sum_{i,k,j} xb[b,x,i] * z[b,z,k] * W[i,k,j] * yb[b,y,j]
// B=8, S=128, D=512; W: [513, 512, 513] fp32.
//
// 3-stage GEMM chain (fp32, packed f32x2 FMA):
//   stage1: T[(b,x), k, j'] = Xb[1024,528] @ Wp[528, 512*528]
//   stage2: Q[(b,x), k, y]  = T_p[512,528] @ Yb_b^T[528,128]   (1024 batches)
//   stage3: out[b,z,x,y]    = Z_b[128,512] @ Q_p[512,128]       (1024 batches)
// j and i padded 513 -> 528 (33 k-tiles of 16) so all tiles are guard-free.
// ---------------------------------------------------------------------------

#define J_PAD 528
#define N1    (512 * J_PAD)      // 270336, stage-1 N / T row length
#define KW    262656             // 512*513, weight (k,j) plane per i

// Scratch (device globals: allocation-free per harness rules)
__device__ float g_Xb[1024 * J_PAD];                       //   2.1 MB
__device__ float g_Yb[1024 * J_PAD];                       //   2.1 MB
__device__ float g_Wp[(size_t)J_PAD * N1];                 // 571   MB
__device__ float g_T [(size_t)1024 * 512 * J_PAD];         // 1.11  GB
__device__ float g_Q [(size_t)1024 * 512 * 128];           // 268   MB

// ---------------- packed f32x2 helpers ----------------
__device__ __forceinline__ unsigned long long dup2(float a) {
    unsigned long long r;
    asm("mov.b64 %0, {%1, %1};" : "=l"(r) : "f"(a));
    return r;
}
__device__ __forceinline__ void ffma2(unsigned long long& c,
                                      unsigned long long a,
                                      unsigned long long b) {
    asm("fma.rn.f32x2 %0, %1, %2, %0;" : "+l"(c) : "l"(a), "l"(b));
}
__device__ __forceinline__ float2 unpk(unsigned long long v) {
    float2 r;
    asm("mov.b64 {%0, %1}, %2;" : "=f"(r.x), "=f"(r.y) : "l"(v));
    return r;
}

// ---------------- prep kernels ----------------
__global__ void prep_xy(const float* __restrict__ x, const float* __restrict__ y) {
    int idx = blockIdx.x * 256 + threadIdx.x;
    if (idx >= 1024 * J_PAD) return;
    int m = idx / J_PAD;
    int j = idx - m * J_PAD;
    float vx, vy;
    if (j < 512)      { vx = x[m * 512 + j]; vy = y[m * 512 + j]; }
    else if (j == 512){ vx = 1.0f;           vy = 1.0f; }
    else              { vx = 0.0f;           vy = 0.0f; }
    g_Xb[idx] = vx;
    g_Yb[idx] = vy;
}

// Repack W [513,512,513] -> Wp [528, 512*528] (zero-padded): makes stage-1
// B-operand loads float4-aligned and guard-free.
__global__ void repack_w(const float* __restrict__ W) {
    int idx = blockIdx.x * 256 + threadIdx.x;   // total 528*270336 = 142,737,408
    int i = idx / N1;
    int r = idx - i * N1;
    int k = r / J_PAD;
    int j = r - k * J_PAD;
    float v = 0.0f;
    if (i < 513 && j < 513) v = W[(size_t)i * KW + k * 513 + j];
    g_Wp[idx] = v;
}

// ---------------- 128x128x16 microkernel (shared) ----------------
// As: duplicated-A ({a,a} u64) [16][128]; Bs: fp32 [16][128].
// Thread computes 8x8 tile at (m0, n0) via 32 f32x2 FMAs per k-step.
__device__ __forceinline__ void mma_tile(const unsigned long long (*As)[128],
                                         const float (*Bsr)[128],
                                         int m0, int n0,
                                         unsigned long long acc[8][4]) {
#pragma unroll
    for (int kk = 0; kk < 16; ++kk) {
        const ulonglong2* pA = reinterpret_cast<const ulonglong2*>(&As[kk][m0]);
        ulonglong2 a0 = pA[0], a1 = pA[1], a2 = pA[2], a3 = pA[3];
        const ulonglong2* pB = reinterpret_cast<const ulonglong2*>(&Bsr[kk][n0]);
        ulonglong2 b0 = pB[0], b1 = pB[1];
        unsigned long long a[8] = {a0.x, a0.y, a1.x, a1.y, a2.x, a2.y, a3.x, a3.y};
        unsigned long long b[4] = {b0.x, b0.y, b1.x, b1.y};
#pragma unroll
        for (int i = 0; i < 8; ++i)
#pragma unroll
            for (int q = 0; q < 4; ++q)
                ffma2(acc[i][q], a[i], b[q]);
    }
}

// ---------------- stage 1: T = Xb @ Wp ----------------
// M=1024, N=270336, K=528. Grid (2112, 8), 256 threads.
__global__ __launch_bounds__(256) void sgemm1() {
    __shared__ __align__(16) unsigned long long As2[2][16][128];  // 32 KB
    __shared__ __align__(16) float              Bs [2][16][128];  // 16 KB
    const int tid  = threadIdx.x;
    const int nblk = blockIdx.x * 128;
    const int mblk = blockIdx.y * 128;
    const int m0 = (tid & 15) * 8;
    const int n0 = (tid >> 4) * 8;
    const int am = tid >> 2,  ac = (tid & 3) * 4;   // A: rows am, am+64
    const int br = tid >> 5,  bc = (tid & 31) * 4;  // B: rows br, br+8

    // prologue: tile 0 -> buffer 0
#pragma unroll
    for (int s = 0; s < 2; ++s) {
        float4 ra = *reinterpret_cast<const float4*>(
            &g_Xb[(mblk + am + s * 64) * J_PAD + ac]);
        As2[0][ac + 0][am + s * 64] = dup2(ra.x);
        As2[0][ac + 1][am + s * 64] = dup2(ra.y);
        As2[0][ac + 2][am + s * 64] = dup2(ra.z);
        As2[0][ac + 3][am + s * 64] = dup2(ra.w);
        float4 rb = *reinterpret_cast<const float4*>(
            &g_Wp[(size_t)(br + s * 8) * N1 + nblk + bc]);
        *reinterpret_cast<float4*>(&Bs[0][br + s * 8][bc]) = rb;
    }
    __syncthreads();

    unsigned long long acc[8][4];
#pragma unroll
    for (int i = 0; i < 8; ++i)
#pragma unroll
        for (int q = 0; q < 4; ++q) acc[i][q] = 0ull;

    const int KT = J_PAD / 16;  // 33
    for (int kt = 0; kt < KT; ++kt) {
        const int cur = kt & 1;
        float4 pa0, pa1, pb0, pb1;
        const bool pre = (kt + 1 < KT);
        if (pre) {
            pa0 = *reinterpret_cast<const float4*>(
                &g_Xb[(mblk + am) * J_PAD + (kt + 1) * 16 + ac]);
            pa1 = *reinterpret_cast<const float4*>(
                &g_Xb[(mblk + am + 64) * J_PAD + (kt + 1) * 16 + ac]);
            pb0 = *reinterpret_cast<const float4*>(
                &g_Wp[(size_t)((kt + 1) * 16 + br) * N1 + nblk + bc]);
            pb1 = *reinterpret_cast<const float4*>(
                &g_Wp[(size_t)((kt + 1) * 16 + br + 8) * N1 + nblk + bc]);
        }
        mma_tile(As2[cur], Bs[cur], m0, n0, acc);
        if (pre) {
            const int nx = cur ^ 1;
            As2[nx][ac + 0][am]      = dup2(pa0.x);
            As2[nx][ac + 1][am]      = dup2(pa0.y);
            As2[nx][ac + 2][am]      = dup2(pa0.z);
            As2[nx][ac + 3][am]      = dup2(pa0.w);
            As2[nx][ac + 0][am + 64] = dup2(pa1.x);
            As2[nx][ac + 1][am + 64] = dup2(pa1.y);
            As2[nx][ac + 2][am + 64] = dup2(pa1.z);
            As2[nx][ac + 3][am + 64] = dup2(pa1.w);
            *reinterpret_cast<float4*>(&Bs[nx][br][bc])     = pb0;
            *reinterpret_cast<float4*>(&Bs[nx][br + 8][bc]) = pb1;
        }
        __syncthreads();
    }

#pragma unroll
    for (int i = 0; i < 8; ++i) {
        float2 t0 = unpk(acc[i][0]), t1 = unpk(acc[i][1]);
        float2 t2 = unpk(acc[i][2]), t3 = unpk(acc[i][3]);
        float* dst = &g_T[(size_t)(mblk + m0 + i) * N1 + nblk + n0];
        *reinterpret_cast<float4*>(dst)     = make_float4(t0.x, t0.y, t1.x, t1.y);
        *reinterpret_cast<float4*>(dst + 4) = make_float4(t2.x, t2.y, t3.x, t3.y);
    }
}

// ---------------- stage 2: Q_p = T_p @ Yb_b^T ----------------
// Per batch p=(b,x): M=512(k), N=128(y), K=528(j). Grid (4, 1024).
__global__ __launch_bounds__(256) void sgemm2() {
    __shared__ __align__(16) unsigned long long As2[2][16][128];
    __shared__ __align__(16) float              Bs [2][16][128];
    const int tid  = threadIdx.x;
    const int mblk = blockIdx.x * 128;
    const int p    = blockIdx.y;
    const int b    = p >> 7;
    const float* Ap = &g_T [(size_t)p * 512 * J_PAD];
    const float* Bp = &g_Yb[(size_t)b * 128 * J_PAD];
    const int m0 = (tid & 15) * 8;
    const int n0 = (tid >> 4) * 8;
    const int am = tid >> 2, ac = (tid & 3) * 4;   // A rows am, am+64
    const int yv = tid >> 2, yc = (tid & 3) * 4;   // B (transposed): y rows yv, yv+64

#pragma unroll
    for (int s = 0; s < 2; ++s) {
        float4 ra = *reinterpret_cast<const float4*>(
            &Ap[(mblk + am + s * 64) * J_PAD + ac]);
        As2[0][ac + 0][am + s * 64] = dup2(ra.x);
        As2[0][ac + 1][am + s * 64] = dup2(ra.y);
        As2[0][ac + 2][am + s * 64] = dup2(ra.z);
        As2[0][ac + 3][am + s * 64] = dup2(ra.w);
        float4 rb = *reinterpret_cast<const float4*>(
            &Bp[(yv + s * 64) * J_PAD + yc]);
        Bs[0][yc + 0][yv + s * 64] = rb.x;
        Bs[0][yc + 1][yv + s * 64] = rb.y;
        Bs[0][yc + 2][yv + s * 64] = rb.z;
        Bs[0][yc + 3][yv + s * 64] = rb.w;
    }
    __syncthreads();

    unsigned long long acc[8][4];
#pragma unroll
    for (int i = 0; i < 8; ++i)
#pragma unroll
        for (int q = 0; q < 4; ++q) acc[i][q] = 0ull;

    const int KT = J_PAD / 16;  // 33
    for (int kt = 0; kt < KT; ++kt) {
        const int cur = kt & 1;
        float4 pa0, pa1, pb0, pb1;
        const bool pre = (kt + 1 < KT);
        if (pre) {
            pa0 = *reinterpret_cast<const float4*>(
                &Ap[(mblk + am) * J_PAD + (kt + 1) * 16 + ac]);
            pa1 = *reinterpret_cast<const float4*>(
                &Ap[(mblk + am + 64) * J_PAD + (kt + 1) * 16 + ac]);
            pb0 = *reinterpret_cast<const float4*>(
                &Bp[yv * J_PAD + (kt + 1) * 16 + yc]);
            pb1 = *reinterpret_cast<const float4*>(
                &Bp[(yv + 64) * J_PAD + (kt + 1) * 16 + yc]);
        }
        mma_tile(As2[cur], Bs[cur], m0, n0, acc);
        if (pre) {
            const int nx = cur ^ 1;
            As2[nx][ac + 0][am]      = dup2(pa0.x);
            As2[nx][ac + 1][am]      = dup2(pa0.y);
            As2[nx][ac + 2][am]      = dup2(pa0.z);
            As2[nx][ac + 3][am]      = dup2(pa0.w);
            As2[nx][ac + 0][am + 64] = dup2(pa1.x);
            As2[nx][ac + 1][am + 64] = dup2(pa1.y);
            As2[nx][ac + 2][am + 64] = dup2(pa1.z);
            As2[nx][ac + 3][am + 64] = dup2(pa1.w);
            Bs[nx][yc + 0][yv]      = pb0.x;
            Bs[nx][yc + 1][yv]      = pb0.y;
            Bs[nx][yc + 2][yv]      = pb0.z;
            Bs[nx][yc + 3][yv]      = pb0.w;
            Bs[nx][yc + 0][yv + 64] = pb1.x;
            Bs[nx][yc + 1][yv + 64] = pb1.y;
            Bs[nx][yc + 2][yv + 64] = pb1.z;
            Bs[nx][yc + 3][yv + 64] = pb1.w;
        }
        __syncthreads();
    }

#pragma unroll
    for (int i = 0; i < 8; ++i) {
        float2 t0 = unpk(acc[i][0]), t1 = unpk(acc[i][1]);
        float2 t2 = unpk(acc[i][2]), t3 = unpk(acc[i][3]);
        float* dst = &g_Q[(size_t)p * 512 * 128 +
                          (size_t)(mblk + m0 + i) * 128 + n0];
        *reinterpret_cast<float4*>(dst)     = make_float4(t0.x, t0.y, t1.x, t1.y);
        *reinterpret_cast<float4*>(dst + 4) = make_float4(t2.x, t2.y, t3.x, t3.y);
    }
}

// ---------------- stage 3: out_bx = Z_b @ Q_p ----------------
// Per batch p=(b,x): M=128(z), N=128(y), K=512. Grid (1024).
__global__ __launch_bounds__(256) void sgemm3(const float* __restrict__ Z,
                                              float* __restrict__ Out) {
    __shared__ __align__(16) unsigned long long As2[2][16][128];
    __shared__ __align__(16) float              Bs [2][16][128];
    const int tid = threadIdx.x;
    const int p   = blockIdx.x;
    const int b   = p >> 7;
    const int x   = p & 127;
    const float* Ap = Z   + (size_t)b * 128 * 512;
    const float* Bp = &g_Q[(size_t)p * 512 * 128];
    float* Cp = Out + (size_t)b * 2097152 + (size_t)x * 128;
    const int m0 = (tid & 15) * 8;
    const int n0 = (tid >> 4) * 8;
    const int am = tid >> 2,  ac = (tid & 3) * 4;
    const int br = tid >> 5,  bc = (tid & 31) * 4;

#pragma unroll
    for (int s = 0; s < 2; ++s) {
        float4 ra = *reinterpret_cast<const float4*>(
            &Ap[(am + s * 64) * 512 + ac]);
        As2[0][ac + 0][am + s * 64] = dup2(ra.x);
        As2[0][ac + 1][am + s * 64] = dup2(ra.y);
        As2[0][ac + 2][am + s * 64] = dup2(ra.z);
        As2[0][ac + 3][am + s * 64] = dup2(ra.w);
        float4 rb = *reinterpret_cast<const float4*>(
            &Bp[(br + s * 8) * 128 + bc]);
        *reinterpret_cast<float4*>(&Bs[0][br + s * 8][bc]) = rb;
    }
    __syncthreads();

    unsigned long long acc[8][4];
#pragma unroll
    for (int i = 0; i < 8; ++i)
#pragma unroll
        for (int q = 0; q < 4; ++q) acc[i][q] = 0ull;

    const int KT = 512 / 16;  // 32
    for (int kt = 0; kt < KT; ++kt) {
        const int cur = kt & 1;
        float4 pa0, pa1, pb0, pb1;
        const bool pre = (kt + 1 < KT);
        if (pre) {
            pa0 = *reinterpret_cast<const float4*>(
                &Ap[am * 512 + (kt + 1) * 16 + ac]);
            pa1 = *reinterpret_cast<const float4*>(
                &Ap[(am + 64) * 512 + (kt + 1) * 16 + ac]);
            pb0 = *reinterpret_cast<const float4*>(
                &Bp[((kt + 1) * 16 + br) * 128 + bc]);
            pb1 = *reinterpret_cast<const float4*>(
                &Bp[((kt + 1) * 16 + br + 8) * 128 + bc]);
        }
        mma_tile(As2[cur], Bs[cur], m0, n0, acc);
        if (pre) {
            const int nx = cur ^ 1;
            As2[nx][ac + 0][am]      = dup2(pa0.x);
            As2[nx][ac + 1][am]      = dup2(pa0.y);
            As2[nx][ac + 2][am]      = dup2(pa0.z);
            As2[nx][ac + 3][am]      = dup2(pa0.w);
            As2[nx][ac + 0][am + 64] = dup2(pa1.x);
            As2[nx][ac + 1][am + 64] = dup2(pa1.y);
            As2[nx][ac + 2][am + 64] = dup2(pa1.z);
            As2[nx][ac + 3][am + 64] = dup2(pa1.w);
            *reinterpret_cast<float4*>(&Bs[nx][br][bc])     = pb0;
            *reinterpret_cast<float4*>(&Bs[nx][br + 8][bc]) = pb1;
        }
        __syncthreads();
    }

#pragma unroll
    for (int i = 0; i < 8; ++i) {
        float2 t0 = unpk(acc[i][0]), t1 = unpk(acc[i][1]);
        float2 t2 = unpk(acc[i][2]), t3 = unpk(acc[i][3]);
        float* dst = Cp + (size_t)(m0 + i) * 16384 + n0;
        *reinterpret_cast<float4*>(dst)     = make_float4(t0.x, t0.y, t1.x, t1.y);
        *reinterpret_cast<float4*>(dst + 4) = make_float4(t2.x, t2.y, t3.x, t3.y);
    }
}

// ---------------- launcher ----------------
extern "C" void kernel_launch(void* const* d_in, const int* in_sizes, int n_in,
                              void* d_out, int out_size) {
    // weight = the largest input; x, y, z = remaining three, in metadata order
    int wi = 0;
    for (int i = 1; i < n_in; ++i)
        if (in_sizes[i] > in_sizes[wi]) wi = i;
    const float* xyz[3] = {nullptr, nullptr, nullptr};
    int c = 0;
    for (int i = 0; i < n_in; ++i)
        if (i != wi && c < 3) xyz[c++] = (const float*)d_in[i];
    const float* x = xyz[0];
    const float* y = xyz[1];
    const float* z = xyz[2];
    const float* w = (const float*)d_in[wi];
    float* out = (float*)d_out;

    prep_xy<<<(1024 * J_PAD) / 256, 256>>>(x, y);
    repack_w<<<(int)(((size_t)J_PAD * N1) / 256), 256>>>(w);

    dim3 g1(N1 / 128, 1024 / 128);   // (2112, 8)
    sgemm1<<<g1, 256>>>();

    dim3 g2(512 / 128, 1024);        // (4, 1024)
    sgemm2<<<g2, 256>>>();

    sgemm3<<<1024, 256>>>(z, out);
}

// round 17
// speedup vs baseline: 5.9095x; 5.9018x over previous
#include <cuda_runtime.h>
#include <cuda_bf16.h>
#include <cstdint>

// ---------------------------------------------------------------------------
// Triaffine via warp-level bf16 mma.sync (plain compute_103-legal PTX).
//  stage1: T[(b,x),(k,j)] = Xb[1024,576] @ Wt[(k,j),576]^T
//  stage2: Qt[p][y][k]    = (T_p[512,576] @ Yb_b[128,576]^T)^T
//  stage3: out[b,z,x,y]   = Z_b[128,512] @ Qt_p[128,512]^T
// Split precision: v = hi + lo (bf16); C = Ah*Bh + Ah*Bl + Al*Bh (fp32 accum).
// ---------------------------------------------------------------------------

#define KD 576
#define N1 294912  // 512*KD

__device__ __nv_bfloat16 g_Xh[1024*KD], g_Xl[1024*KD];
__device__ __nv_bfloat16 g_Yh[1024*KD], g_Yl[1024*KD];
__device__ __nv_bfloat16 g_Zh[1024*512], g_Zl[1024*512];
__device__ __nv_bfloat16 g_Wth[(size_t)N1*KD], g_Wtl[(size_t)N1*KD];
__device__ __nv_bfloat16 g_Th[(size_t)1024*N1], g_Tl[(size_t)1024*N1];
__device__ __nv_bfloat16 g_Qh[(size_t)1024*65536], g_Ql[(size_t)1024*65536];

__device__ __forceinline__ uint32_t s2u(const void* p) {
    uint32_t a;
    asm("{ .reg .u64 t; cvta.to.shared.u64 t, %1; cvt.u32.u64 %0, t; }"
        : "=r"(a) : "l"(p));
    return a;
}
__device__ __forceinline__ void ldm4(uint32_t* r, uint32_t addr) {
    asm volatile("ldmatrix.sync.aligned.m8n8.x4.shared.b16 {%0,%1,%2,%3}, [%4];"
                 : "=r"(r[0]), "=r"(r[1]), "=r"(r[2]), "=r"(r[3]) : "r"(addr));
}
__device__ __forceinline__ void mma16816(float* c, const uint32_t* a,
                                         const uint32_t* b) {
    asm volatile(
        "mma.sync.aligned.m16n8k16.row.col.f32.bf16.bf16.f32 "
        "{%0,%1,%2,%3}, {%4,%5,%6,%7}, {%8,%9}, {%0,%1,%2,%3};"
        : "+f"(c[0]), "+f"(c[1]), "+f"(c[2]), "+f"(c[3])
        : "r"(a[0]), "r"(a[1]), "r"(a[2]), "r"(a[3]), "r"(b[0]), "r"(b[1]));
}
__device__ __forceinline__ void cpa16(uint32_t dst, const void* src) {
    asm volatile("cp.async.cg.shared.global [%0], [%1], 16;"
                 :: "r"(dst), "l"(src));
}
__device__ __forceinline__ void bsplit(float v, __nv_bfloat16& h, __nv_bfloat16& l) {
    h = __float2bfloat16(v);
    l = __float2bfloat16(v - __bfloat162float(h));
}

// ---------------- prep: split x/y (+bias, pad 576) and z ----------------
__global__ void prep_split(const float* __restrict__ x, const float* __restrict__ y,
                           const float* __restrict__ z) {
    int idx = blockIdx.x * 256 + threadIdx.x;   // 1024*576
    int m = idx / KD, j = idx - m * KD;
    float vx = 0.f, vy = 0.f;
    if (j < 512)       { vx = x[m * 512 + j]; vy = y[m * 512 + j]; }
    else if (j == 512) { vx = 1.f;            vy = 1.f; }
    bsplit(vx, g_Xh[idx], g_Xl[idx]);
    bsplit(vy, g_Yh[idx], g_Yl[idx]);
    if (j < 512) { int zi = m * 512 + j; bsplit(z[zi], g_Zh[zi], g_Zl[zi]); }
}

// ---------------- repack: W[i,k,j] -> Wt[(k*576+j)][i] hi/lo ----------------
__global__ void repack_w(const float* __restrict__ W) {
    __shared__ float t[32][33];
    const int i0 = blockIdx.x * 32, j0 = blockIdx.y * 32, kz = blockIdx.z;
    const int tx = threadIdx.x, ty = threadIdx.y;
#pragma unroll
    for (int s = 0; s < 4; ++s) {
        int ii = i0 + ty + s * 8, jj = j0 + tx;
        float v = 0.f;
        if (ii < 513 && jj < 513) v = W[(size_t)ii * 262656 + kz * 513 + jj];
        t[ty + s * 8][tx] = v;
    }
    __syncthreads();
#pragma unroll
    for (int s = 0; s < 4; ++s) {
        int jj = j0 + ty + s * 8, ii = i0 + tx;
        size_t dst = (size_t)(kz * KD + jj) * KD + ii;
        __nv_bfloat16 h, l;
        bsplit(t[tx][ty + s * 8], h, l);
        g_Wth[dst] = h;
        g_Wtl[dst] = l;
    }
}

// ---------------- core: C[128,128] = A[128,K] * B[128,K]^T (3 products) ----
// smem per buffer: Ah,Al,Bh,Bl each 128 rows x 80B (32 bf16 + 16B pad) = 10240B
// EPI 0: bf16 hi/lo row-major; 1: bf16 hi/lo transposed; 2: fp32 row-major.
template <int KC, int EPI>
__device__ __forceinline__ void core(
    const __nv_bfloat16* __restrict__ Ah, const __nv_bfloat16* __restrict__ Al,
    const __nv_bfloat16* __restrict__ Bh, const __nv_bfloat16* __restrict__ Bl,
    int ldk, __nv_bfloat16* oH, __nv_bfloat16* oL, float* oF, int ldo) {
    extern __shared__ char sm[];
    const int tid = threadIdx.x;
    const int lane = tid & 31, w = tid >> 5;
    const int wr = w >> 1, wc = w & 1;           // warp grid 2x2, tile 64x64
    const uint32_t sbase = s2u(sm);

    // per-lane ldmatrix addressing (row stride 80B)
    const int a_ro = ((lane >> 3) & 1) * 8 + (lane & 7);
    const int a_bo = (lane >> 4) * 16;
    const int b_ro = (lane >> 4) * 8 + (lane & 7);
    const int b_bo = ((lane >> 3) & 1) * 16;

    float acc[4][8][4];
#pragma unroll
    for (int mi = 0; mi < 4; ++mi)
#pragma unroll
        for (int ni = 0; ni < 8; ++ni)
#pragma unroll
            for (int q = 0; q < 4; ++q) acc[mi][ni][q] = 0.f;

    // chunk loader: 2048 x 16B cp.async (A 16KB + B 16KB), 16 per thread
    auto load_chunk = [&](int c, int b) {
#pragma unroll
        for (int i = 0; i < 16; ++i) {
            int op = tid + i * 128;
            int o = op >> 9, rem = op & 511;
            int row = rem >> 2, seg = rem & 3;
            const __nv_bfloat16* g = (o == 0) ? Ah : (o == 1) ? Al
                                   : (o == 2) ? Bh : Bl;
            cpa16(sbase + b * 40960 + o * 10240 + row * 80 + seg * 16,
                  g + (size_t)row * ldk + c * 32 + seg * 8);
        }
        asm volatile("cp.async.commit_group;");
    };

    load_chunk(0, 0);
#pragma unroll 1
    for (int c = 0; c < KC; ++c) {
        const int b = c & 1;
        if (c + 1 < KC) {
            load_chunk(c + 1, b ^ 1);
            asm volatile("cp.async.wait_group 1;");
        } else {
            asm volatile("cp.async.wait_group 0;");
        }
        __syncthreads();
        const uint32_t bufo = sbase + b * 40960;
#pragma unroll
        for (int kk = 0; kk < 2; ++kk) {
            const int kb = kk * 32;
            uint32_t af[4][4], bf[4][4], tf[4][4];
#pragma unroll
            for (int mi = 0; mi < 4; ++mi)
                ldm4(af[mi], bufo + (wr * 64 + mi * 16 + a_ro) * 80 + kb + a_bo);
#pragma unroll
            for (int ni = 0; ni < 4; ++ni)
                ldm4(bf[ni], bufo + 20480 +
                             (wc * 64 + ni * 16 + b_ro) * 80 + kb + b_bo);
#pragma unroll
            for (int mi = 0; mi < 4; ++mi)
#pragma unroll
                for (int n8 = 0; n8 < 8; ++n8)
                    mma16816(acc[mi][n8], af[mi], &bf[n8 >> 1][(n8 & 1) * 2]);
#pragma unroll
            for (int ni = 0; ni < 4; ++ni)      // B-lo
                ldm4(tf[ni], bufo + 30720 +
                             (wc * 64 + ni * 16 + b_ro) * 80 + kb + b_bo);
#pragma unroll
            for (int mi = 0; mi < 4; ++mi)
#pragma unroll
                for (int n8 = 0; n8 < 8; ++n8)
                    mma16816(acc[mi][n8], af[mi], &tf[n8 >> 1][(n8 & 1) * 2]);
#pragma unroll
            for (int mi = 0; mi < 4; ++mi)      // A-lo (reuse af regs)
                ldm4(af[mi], bufo + 10240 +
                             (wr * 64 + mi * 16 + a_ro) * 80 + kb + a_bo);
#pragma unroll
            for (int mi = 0; mi < 4; ++mi)
#pragma unroll
                for (int n8 = 0; n8 < 8; ++n8)
                    mma16816(acc[mi][n8], af[mi], &bf[n8 >> 1][(n8 & 1) * 2]);
        }
        __syncthreads();
    }

    // stage C -> smem f32 Ds[128][129]
    float* Ds = reinterpret_cast<float*>(sm);
#pragma unroll
    for (int mi = 0; mi < 4; ++mi)
#pragma unroll
        for (int ni = 0; ni < 8; ++ni) {
            int row = wr * 64 + mi * 16 + (lane >> 2);
            int col = wc * 64 + ni * 8 + (lane & 3) * 2;
            Ds[row * 129 + col]           = acc[mi][ni][0];
            Ds[row * 129 + col + 1]       = acc[mi][ni][1];
            Ds[(row + 8) * 129 + col]     = acc[mi][ni][2];
            Ds[(row + 8) * 129 + col + 1] = acc[mi][ni][3];
        }
    __syncthreads();

    if (EPI == 0) {
        for (int t = tid; t < 8192; t += 128) {
            int r = t >> 6, pc = (t & 63) * 2;
            __nv_bfloat16 h0, l0, h1, l1;
            bsplit(Ds[r * 129 + pc], h0, l0);
            bsplit(Ds[r * 129 + pc + 1], h1, l1);
            __nv_bfloat162 hv; hv.x = h0; hv.y = h1;
            __nv_bfloat162 lv; lv.x = l0; lv.y = l1;
            *reinterpret_cast<__nv_bfloat162*>(oH + (size_t)r * ldo + pc) = hv;
            *reinterpret_cast<__nv_bfloat162*>(oL + (size_t)r * ldo + pc) = lv;
        }
    } else if (EPI == 1) {
        for (int t = tid; t < 8192; t += 128) {
            int y = t >> 6, pk = (t & 63) * 2;
            __nv_bfloat16 h0, l0, h1, l1;
            bsplit(Ds[pk * 129 + y], h0, l0);
            bsplit(Ds[(pk + 1) * 129 + y], h1, l1);
            __nv_bfloat162 hv; hv.x = h0; hv.y = h1;
            __nv_bfloat162 lv; lv.x = l0; lv.y = l1;
            *reinterpret_cast<__nv_bfloat162*>(oH + (size_t)y * ldo + pk) = hv;
            *reinterpret_cast<__nv_bfloat162*>(oL + (size_t)y * ldo + pk) = lv;
        }
    } else {
        for (int t = tid; t < 4096; t += 128) {
            int r = t >> 5, c4 = (t & 31) * 4;
            float4 o = make_float4(Ds[r * 129 + c4],     Ds[r * 129 + c4 + 1],
                                   Ds[r * 129 + c4 + 2], Ds[r * 129 + c4 + 3]);
            *reinterpret_cast<float4*>(oF + (size_t)r * ldo + c4) = o;
        }
    }
}

// ---------------- stage kernels ----------------
__global__ __launch_bounds__(128) void k_s1() {
    const size_t mo = (size_t)blockIdx.x * 128;   // m fastest: 8 tiles share B in L2
    const size_t no = (size_t)blockIdx.y * 128;
    core<18, 0>(g_Xh + mo * KD, g_Xl + mo * KD,
                g_Wth + no * KD, g_Wtl + no * KD, KD,
                g_Th + mo * N1 + no, g_Tl + mo * N1 + no, nullptr, N1);
}
__global__ __launch_bounds__(128) void k_s2() {
    const int mblk = blockIdx.x * 128;
    const int p = blockIdx.y, b = p >> 7;
    core<18, 1>(g_Th + (size_t)p * N1 + (size_t)mblk * KD,
                g_Tl + (size_t)p * N1 + (size_t)mblk * KD,
                g_Yh + (size_t)(b * 128) * KD,
                g_Yl + (size_t)(b * 128) * KD, KD,
                g_Qh + (size_t)p * 65536 + mblk,
                g_Ql + (size_t)p * 65536 + mblk, nullptr, 512);
}
__global__ __launch_bounds__(128) void k_s3(float* __restrict__ out) {
    const int p = blockIdx.x, b = p >> 7, x = p & 127;
    core<16, 2>(g_Zh + (size_t)b * 65536, g_Zl + (size_t)b * 65536,
                g_Qh + (size_t)p * 65536, g_Ql + (size_t)p * 65536, 512,
                nullptr, nullptr,
                out + (size_t)b * 2097152 + (size_t)x * 128, 16384);
}

// ---------------- launcher ----------------
extern "C" void kernel_launch(void* const* d_in, const int* in_sizes, int n_in,
                              void* d_out, int out_size) {
    int wi = 0;
    for (int i = 1; i < n_in; ++i)
        if (in_sizes[i] > in_sizes[wi]) wi = i;
    const float* xyz[3] = {nullptr, nullptr, nullptr};
    int c = 0;
    for (int i = 0; i < n_in; ++i)
        if (i != wi && c < 3) xyz[c++] = (const float*)d_in[i];
    const float* x = xyz[0];
    const float* y = xyz[1];
    const float* z = xyz[2];
    const float* w = (const float*)d_in[wi];

    const int SMEM_BYTES = 81920;   // 2 buffers * 4 operands * 10240B
    cudaFuncSetAttribute(k_s1, cudaFuncAttributeMaxDynamicSharedMemorySize, SMEM_BYTES);
    cudaFuncSetAttribute(k_s2, cudaFuncAttributeMaxDynamicSharedMemorySize, SMEM_BYTES);
    cudaFuncSetAttribute(k_s3, cudaFuncAttributeMaxDynamicSharedMemorySize, SMEM_BYTES);

    prep_split<<<2304, 256>>>(x, y, z);
    repack_w<<<dim3(18, 18, 512), dim3(32, 8)>>>(w);
    k_s1<<<dim3(8, 2304), 128, SMEM_BYTES>>>();
    k_s2<<<dim3(4, 1024), 128, SMEM_BYTES>>>();
    k_s3<<<1024, 128, SMEM_BYTES>>>((float*)d_out);
}